// round 13
// baseline (speedup 1.0000x reference)
#include <cuda_runtime.h>
#include <cstdint>

#define T_STEPS 1000
#define BATCH   8192
#define IN      9
#define HID     96
#define OUTD    3
#define GRP     16
#define HS      6
#define HP      3
#define CH      5                    // timesteps per staged chunk
#define NC      (T_STEPS / CH)       // 200 chunks
#define BPB     8                    // batches per block
#define ROWP    10                   // padded u64 slots per (t, batch) row
#define CHF     (CH * BPB * IN)      // valid elements per chunk = 360
#define NLD     3                    // ceil(360/128)

typedef unsigned long long u64;

union f2u {
    u64 u;
    float f[2];
};

__device__ __forceinline__ u64 pack2(float lo, float hi) {
    f2u v; v.f[0] = lo; v.f[1] = hi; return v.u;
}
__device__ __forceinline__ u64 ffma2(u64 a, u64 b, u64 c) {
    u64 d;
    asm("fma.rn.f32x2 %0, %1, %2, %3;" : "=l"(d) : "l"(a), "l"(b), "l"(c));
    return d;
}

__global__ __launch_bounds__(128, 5)
void snn_kernel(const float* __restrict__ X,
                const float* __restrict__ W1,
                const float* __restrict__ B1,
                const float* __restrict__ W2,
                const float* __restrict__ B2,
                float* __restrict__ out)
{
    __shared__ alignas(16) u64 xs[2][CH * BPB * ROWP];  // x pre-duplicated {f,f}

    const int tix  = threadIdx.x;
    const int pos  = tix & 15;                 // lane within 16-thread group
    const int bl   = tix >> 4;                 // local batch 0..7
    const int b    = blockIdx.x * BPB + bl;    // global batch element
    const int hbase = pos * HS;
    const int ch   = pos & 3;                  // this lane's channel (3 = idle)
    const int chc  = (ch < 3) ? ch : 2;

    // ---- Weight slices to registers ----
    u64 w1p[IN][HP];
#pragma unroll
    for (int j = 0; j < HP; j++) {
        const int h0 = hbase + 2 * j;
#pragma unroll
        for (int i = 0; i < IN; i++)
            w1p[i][j] = pack2(W1[h0 * IN + i], W1[(h0 + 1) * IN + i]);
    }
    u64 b1p[HP];
#pragma unroll
    for (int j = 0; j < HP; j++)
        b1p[j] = pack2(B1[hbase + 2 * j], B1[hbase + 2 * j + 1]);

    u64 w2p[OUTD][HP];
#pragma unroll
    for (int o = 0; o < OUTD; o++)
#pragma unroll
        for (int j = 0; j < HP; j++)
            w2p[o][j] = pack2(W2[o * HID + hbase + 2 * j],
                              W2[o * HID + hbase + 2 * j + 1]);

    const float bk = B2[chc];

    const u64 BETA2 = 0x3F6B851F3F6B851Full;   // {0.92, 0.92}
    u64 NEGINVB2;
    { f2u v; v.f[0] = -(1.0f / 0.92f); v.f[1] = v.f[0]; NEGINVB2 = v.u; }

    // ---- State (tilde fold: m~ = m - s/beta => m_t = beta*m~ + cur) ----
    u64 mt[HP];
#pragma unroll
    for (int j = 0; j < HP; j++) mt[j] = 0ull;
    float mloc = 0.f, sloc = 0.f;

    const int orow    = BATCH * OUTD;
    const int memoff  = T_STEPS * orow;
    const int cstride = CH * BATCH * IN;

    // writer lanes: pos 0-2 -> spk2[ch], pos 4-6 -> mem2[ch]
    const bool writer = (ch < 3) && (pos < 8);
    const bool is_spk = (pos < 4);
    float* stp = out + b * OUTD + chc + (is_spk ? 0 : memoff);

    // ---- Prologue: stage chunk 0 (offsets recomputed, not cached) ----
    float stage[NLD];
#pragma unroll
    for (int k = 0; k < NLD; k++) {
        const int j = tix + 128 * k;
        if (j < CHF) {
            const int tl  = j / (BPB * IN);
            const int rem = j - tl * (BPB * IN);
            stage[k] = __ldg(X + tl * (BATCH * IN) + blockIdx.x * (BPB * IN) + rem);
        }
    }
#pragma unroll
    for (int k = 0; k < NLD; k++) {
        const int j = tix + 128 * k;
        if (j < CHF) {
            const int tl  = j / (BPB * IN);
            const int rem = j - tl * (BPB * IN);
            const int bll = rem / IN;
            const int ii  = rem - bll * IN;
            xs[0][(tl * BPB + bll) * ROWP + ii] = pack2(stage[k], stage[k]);
        }
    }
    __syncthreads();

#pragma unroll 1
    for (int c = 0; c < NC; c++) {
        const bool more = (c + 1 < NC);
        if (more) {
            const float* xb = X + (c + 1) * cstride;
#pragma unroll
            for (int k = 0; k < NLD; k++) {
                const int j = tix + 128 * k;
                if (j < CHF) {
                    const int tl  = j / (BPB * IN);
                    const int rem = j - tl * (BPB * IN);
                    stage[k] = __ldg(xb + tl * (BATCH * IN)
                                     + blockIdx.x * (BPB * IN) + rem);
                }
            }
        }

        const u64* xrow = &xs[c & 1][bl * ROWP];

#pragma unroll 2
        for (int s = 0; s < CH; s++) {
            // layer 1: m = beta*m~ + b1 + x@W1slice  (R9 chained form)
            u64 mp[HP];
#pragma unroll
            for (int j = 0; j < HP; j++)
                mp[j] = ffma2(BETA2, mt[j], b1p[j]);
#pragma unroll
            for (int i = 0; i < IN; i++) {
                const u64 xd = xrow[i];
#pragma unroll
                for (int j = 0; j < HP; j++)
                    mp[j] = ffma2(xd, w1p[i][j], mp[j]);
            }
            xrow += BPB * ROWP;

            // spike + reset fold + layer-2 partials
            u64 c0 = 0ull, c1 = 0ull, c2 = 0ull;
#pragma unroll
            for (int j = 0; j < HP; j++) {
                f2u m; m.u = mp[j];
                f2u sv;
                sv.f[0] = (m.f[0] > 1.0f) ? 1.0f : 0.0f;
                sv.f[1] = (m.f[1] > 1.0f) ? 1.0f : 0.0f;
                mt[j] = ffma2(sv.u, NEGINVB2, mp[j]);
                c0 = ffma2(sv.u, w2p[0][j], c0);
                c1 = ffma2(sv.u, w2p[1][j], c1);
                c2 = ffma2(sv.u, w2p[2][j], c2);
            }
            f2u a0, a1, a2;
            a0.u = c0; a1.u = c1; a2.u = c2;
            float r0 = a0.f[0] + a0.f[1];
            float r1 = a1.f[0] + a1.f[1];
            float r2 = a2.f[0] + a2.f[1];

            // levels 1,2 on all channels (quad sums)
            r0 += __shfl_xor_sync(0xffffffffu, r0, 1);
            r1 += __shfl_xor_sync(0xffffffffu, r1, 1);
            r2 += __shfl_xor_sync(0xffffffffu, r2, 1);
            r0 += __shfl_xor_sync(0xffffffffu, r0, 2);
            r1 += __shfl_xor_sync(0xffffffffu, r1, 2);
            r2 += __shfl_xor_sync(0xffffffffu, r2, 2);

            // select own channel (pos&3 invariant under xor 4/8), finish
            float v = r0;
            v = (ch == 1) ? r1 : v;
            v = (ch == 2) ? r2 : v;
            v += __shfl_xor_sync(0xffffffffu, v, 4);
            v += __shfl_xor_sync(0xffffffffu, v, 8);

            // per-lane mem2 for this lane's channel
            mloc = fmaf(0.92f, mloc, v + bk) - sloc;
            sloc = (mloc > 1.0f) ? 1.0f : 0.0f;

            if (writer) *stp = is_spk ? sloc : mloc;
            stp += orow;
        }

        if (more) {
#pragma unroll
            for (int k = 0; k < NLD; k++) {
                const int j = tix + 128 * k;
                if (j < CHF) {
                    const int tl  = j / (BPB * IN);
                    const int rem = j - tl * (BPB * IN);
                    const int bll = rem / IN;
                    const int ii  = rem - bll * IN;
                    xs[(c + 1) & 1][(tl * BPB + bll) * ROWP + ii] =
                        pack2(stage[k], stage[k]);
                }
            }
            __syncthreads();
        }
    }
}

extern "C" void kernel_launch(void* const* d_in, const int* in_sizes, int n_in,
                              void* d_out, int out_size)
{
    const float* X  = (const float*)d_in[0];
    const float* W1 = (const float*)d_in[1];
    const float* B1 = (const float*)d_in[2];
    const float* W2 = (const float*)d_in[3];
    const float* B2 = (const float*)d_in[4];
    float* out = (float*)d_out;

    snn_kernel<<<BATCH / BPB, 128>>>(X, W1, B1, W2, B2, out);  // 1024 blocks
}

// round 14
// speedup vs baseline: 1.4022x; 1.4022x over previous
#include <cuda_runtime.h>
#include <cstdint>

#define T_STEPS 1000
#define BATCH   8192
#define IN      9
#define HID     96
#define OUTD    3
#define GRP     16
#define HS      6
#define HP      3
#define CH      10                   // timesteps per staged chunk
#define NC      (T_STEPS / CH)       // 100 chunks
#define BPB     8                    // batches per block
#define ROWP    10                   // padded u64 slots per (t, batch) row
#define CHF     (CH * BPB * IN)      // valid elements per chunk = 720
#define NLD     6                    // ceil(720/128)

typedef unsigned long long u64;

union f2u {
    u64 u;
    float f[2];
};

__device__ __forceinline__ u64 pack2(float lo, float hi) {
    f2u v; v.f[0] = lo; v.f[1] = hi; return v.u;
}
__device__ __forceinline__ u64 ffma2(u64 a, u64 b, u64 c) {
    u64 d;
    asm("fma.rn.f32x2 %0, %1, %2, %3;" : "=l"(d) : "l"(a), "l"(b), "l"(c));
    return d;
}

__global__ __launch_bounds__(128, 4)
void snn_kernel(const float* __restrict__ X,
                const float* __restrict__ W1,
                const float* __restrict__ B1,
                const float* __restrict__ W2,
                const float* __restrict__ B2,
                float* __restrict__ out)
{
    __shared__ alignas(16) u64 xs[2][CH * BPB * ROWP];  // x pre-duplicated {f,f}

    const int tix  = threadIdx.x;
    const int pos  = tix & 15;                 // lane within 16-thread group
    const int lane = tix & 31;                 // warp lane
    const int bl   = tix >> 4;                 // local batch 0..7
    const int b    = blockIdx.x * BPB + bl;    // global batch element
    const int hbase = pos * HS;
    const int ch   = pos & 3;                  // this lane's channel (3 = idle)
    const int chc  = (ch < 3) ? ch : 2;

    // rotation-reduction source lanes (within each quad), hoisted
    const int src1 = (lane & ~3) | ((lane + 1) & 3);
    const int src2 = (lane & ~3) | ((lane + 2) & 3);
    const int src3 = (lane & ~3) | ((lane + 3) & 3);

    // ---- Weight slices to registers ----
    u64 w1p[IN][HP];
#pragma unroll
    for (int j = 0; j < HP; j++) {
        const int h0 = hbase + 2 * j;
#pragma unroll
        for (int i = 0; i < IN; i++)
            w1p[i][j] = pack2(W1[h0 * IN + i], W1[(h0 + 1) * IN + i]);
    }
    u64 b1p[HP];
#pragma unroll
    for (int j = 0; j < HP; j++)
        b1p[j] = pack2(B1[hbase + 2 * j], B1[hbase + 2 * j + 1]);

    u64 w2p[OUTD][HP];
#pragma unroll
    for (int o = 0; o < OUTD; o++)
#pragma unroll
        for (int j = 0; j < HP; j++)
            w2p[o][j] = pack2(W2[o * HID + hbase + 2 * j],
                              W2[o * HID + hbase + 2 * j + 1]);

    const float bk = B2[chc];

    const u64 BETA2 = 0x3F6B851F3F6B851Full;   // {0.92, 0.92}
    u64 NEGINVB2;
    { f2u v; v.f[0] = -(1.0f / 0.92f); v.f[1] = v.f[0]; NEGINVB2 = v.u; }

    // ---- State (tilde fold: m~ = m - s/beta => m_t = beta*m~ + cur) ----
    u64 mt[HP];
#pragma unroll
    for (int j = 0; j < HP; j++) mt[j] = 0ull;
    float mloc = 0.f, sloc = 0.f;

    const int orow    = BATCH * OUTD;
    const int memoff  = T_STEPS * orow;
    const int cstride = CH * BATCH * IN;

    // writer lanes: pos 0-2 -> spk2[ch], pos 4-6 -> mem2[ch]
    const bool writer = (ch < 3) && (pos < 8);
    const bool is_spk = (pos < 4);
    float* stp = out + b * OUTD + chc + (is_spk ? 0 : memoff);

    // ---- Cooperative-load offsets + padded smem slots (computed once) ----
    int offk[NLD], slotk[NLD];
#pragma unroll
    for (int k = 0; k < NLD; k++) {
        const int j   = tix + 128 * k;         // 0..767 (valid < 720)
        const int tl  = j / (BPB * IN);
        const int rem = j - tl * (BPB * IN);
        const int bll = rem / IN;
        const int ii  = rem - bll * IN;
        offk[k]  = tl * (BATCH * IN) + blockIdx.x * (BPB * IN) + rem;
        slotk[k] = (tl * BPB + bll) * ROWP + ii;
    }

    // ---- Prologue: stage chunk 0 ----
    float stage[NLD];
#pragma unroll
    for (int k = 0; k < NLD; k++)
        if (tix + 128 * k < CHF) stage[k] = __ldg(X + offk[k]);
#pragma unroll
    for (int k = 0; k < NLD; k++)
        if (tix + 128 * k < CHF) xs[0][slotk[k]] = pack2(stage[k], stage[k]);
    __syncthreads();

#pragma unroll 1
    for (int c = 0; c < NC; c++) {
        const bool more = (c + 1 < NC);
        if (more) {
            const float* xb = X + (c + 1) * cstride;
#pragma unroll
            for (int k = 0; k < NLD; k++)
                if (tix + 128 * k < CHF) stage[k] = __ldg(xb + offk[k]);
        }

        const u64* xrow = &xs[c & 1][bl * ROWP];

#pragma unroll 2
        for (int s = 0; s < CH; s++) {
            // layer 1: m = beta*m~ + b1 + x@W1slice
            u64 mp[HP];
#pragma unroll
            for (int j = 0; j < HP; j++)
                mp[j] = ffma2(BETA2, mt[j], b1p[j]);
#pragma unroll
            for (int i = 0; i < IN; i++) {
                const u64 xd = xrow[i];
#pragma unroll
                for (int j = 0; j < HP; j++)
                    mp[j] = ffma2(xd, w1p[i][j], mp[j]);
            }
            xrow += BPB * ROWP;

            // spike + reset fold + layer-2 partials
            u64 c0 = 0ull, c1 = 0ull, c2 = 0ull;
#pragma unroll
            for (int j = 0; j < HP; j++) {
                f2u m; m.u = mp[j];
                f2u sv;
                sv.f[0] = (m.f[0] > 1.0f) ? 1.0f : 0.0f;
                sv.f[1] = (m.f[1] > 1.0f) ? 1.0f : 0.0f;
                mt[j] = ffma2(sv.u, NEGINVB2, mp[j]);
                c0 = ffma2(sv.u, w2p[0][j], c0);
                c1 = ffma2(sv.u, w2p[1][j], c1);
                c2 = ffma2(sv.u, w2p[2][j], c2);
            }
            f2u a0, a1, a2;
            a0.u = c0; a1.u = c1; a2.u = c2;
            const float r0 = a0.f[0] + a0.f[1];
            const float r1 = a1.f[0] + a1.f[1];
            const float r2 = a2.f[0] + a2.f[1];

            // ---- rotation reduction within each quad: 3 independent shfl ----
            // round m: this lane sends r[(ch-m)&3] (3 = don't care),
            // receives its own channel's partial from lane (lane&~3)|((lane+m)&3)
            const float own = (ch == 1) ? r1 : ((ch == 2) ? r2 : r0);
            const float s1v = (ch == 1) ? r0 : ((ch == 2) ? r1 : r2);
            const float s2v = (ch == 0) ? r2 : ((ch == 2) ? r0 : r1);
            const float s3v = (ch == 0) ? r1 : ((ch == 1) ? r2 : r0);

            const float g1 = __shfl_sync(0xffffffffu, s1v, src1);
            const float g2 = __shfl_sync(0xffffffffu, s2v, src2);
            const float g3 = __shfl_sync(0xffffffffu, s3v, src3);
            float v = (own + g1) + (g2 + g3);   // quad total of own channel

            // sum the 4 quads of the 16-lane group
            v += __shfl_xor_sync(0xffffffffu, v, 4);
            v += __shfl_xor_sync(0xffffffffu, v, 8);

            // per-lane mem2 for this lane's channel
            mloc = fmaf(0.92f, mloc, v + bk) - sloc;
            sloc = (mloc > 1.0f) ? 1.0f : 0.0f;

            if (writer) *stp = is_spk ? sloc : mloc;
            stp += orow;
        }

        if (more) {
#pragma unroll
            for (int k = 0; k < NLD; k++)
                if (tix + 128 * k < CHF)
                    xs[(c + 1) & 1][slotk[k]] = pack2(stage[k], stage[k]);
            __syncthreads();
        }
    }
}

extern "C" void kernel_launch(void* const* d_in, const int* in_sizes, int n_in,
                              void* d_out, int out_size)
{
    const float* X  = (const float*)d_in[0];
    const float* W1 = (const float*)d_in[1];
    const float* B1 = (const float*)d_in[2];
    const float* W2 = (const float*)d_in[3];
    const float* B2 = (const float*)d_in[4];
    float* out = (float*)d_out;

    snn_kernel<<<BATCH / BPB, 128>>>(X, W1, B1, W2, B2, out);  // 1024 blocks
}

// round 15
// speedup vs baseline: 1.5912x; 1.1348x over previous
#include <cuda_runtime.h>
#include <cstdint>

#define T_STEPS 1000
#define BATCH   8192
#define IN      9
#define HID     96
#define OUTD    3
#define GRP     16
#define HS      6
#define HP      3
#define CH      10                   // timesteps per staged chunk
#define NC      (T_STEPS / CH)       // 100 chunks
#define BPB     8                    // batches per block
#define ROWP    10                   // padded u64 slots per (t, batch) row
#define CHF     (CH * BPB * IN)      // valid elements per chunk = 720
#define NLD     6                    // ceil(720/128)

#define ONE_BITS 0x3F800000          // bit pattern of 1.0f

typedef unsigned long long u64;

union f2u {
    u64 u;
    float f[2];
};

__device__ __forceinline__ u64 pack2(float lo, float hi) {
    f2u v; v.f[0] = lo; v.f[1] = hi; return v.u;
}
__device__ __forceinline__ u64 ffma2(u64 a, u64 b, u64 c) {
    u64 d;
    asm("fma.rn.f32x2 %0, %1, %2, %3;" : "=l"(d) : "l"(a), "l"(b), "l"(c));
    return d;
}
// spike = (m > 1.0f) ? 1.0f : 0.0f via integer compare (alu pipe, not fma).
// Valid for all finite m: positive floats compare as ints; negative m has
// negative int representation < 0x3F800000.
__device__ __forceinline__ float spike_i(float m) {
    return (__float_as_int(m) > ONE_BITS) ? 1.0f : 0.0f;
}

__global__ __launch_bounds__(128, 4)
void snn_kernel(const float* __restrict__ X,
                const float* __restrict__ W1,
                const float* __restrict__ B1,
                const float* __restrict__ W2,
                const float* __restrict__ B2,
                float* __restrict__ out)
{
    __shared__ alignas(16) u64 xs[2][CH * BPB * ROWP];  // x pre-duplicated {f,f}

    const int tix  = threadIdx.x;
    const int pos  = tix & 15;                 // lane within 16-thread group
    const int bl   = tix >> 4;                 // local batch 0..7
    const int b    = blockIdx.x * BPB + bl;    // global batch element
    const int hbase = pos * HS;
    const int ch   = pos & 3;                  // this lane's channel (3 = idle)
    const int chc  = (ch < 3) ? ch : 2;

    // ---- Weight slices to registers ----
    u64 w1p[IN][HP];
#pragma unroll
    for (int j = 0; j < HP; j++) {
        const int h0 = hbase + 2 * j;
#pragma unroll
        for (int i = 0; i < IN; i++)
            w1p[i][j] = pack2(W1[h0 * IN + i], W1[(h0 + 1) * IN + i]);
    }
    u64 b1p[HP];
#pragma unroll
    for (int j = 0; j < HP; j++)
        b1p[j] = pack2(B1[hbase + 2 * j], B1[hbase + 2 * j + 1]);

    u64 w2p[OUTD][HP];
#pragma unroll
    for (int o = 0; o < OUTD; o++)
#pragma unroll
        for (int j = 0; j < HP; j++)
            w2p[o][j] = pack2(W2[o * HID + hbase + 2 * j],
                              W2[o * HID + hbase + 2 * j + 1]);

    const float bk = B2[chc];

    const u64 BETA2 = 0x3F6B851F3F6B851Full;   // {0.92, 0.92}
    u64 NEGINVB2;
    { f2u v; v.f[0] = -(1.0f / 0.92f); v.f[1] = v.f[0]; NEGINVB2 = v.u; }

    // ---- State (tilde fold: m~ = m - s/beta => m_t = beta*m~ + cur) ----
    u64 mt[HP];
#pragma unroll
    for (int j = 0; j < HP; j++) mt[j] = 0ull;
    float mloc = 0.f, sloc = 0.f;

    const int orow    = BATCH * OUTD;
    const int memoff  = T_STEPS * orow;
    const int cstride = CH * BATCH * IN;

    // writer lanes: pos 0-2 -> spk2[ch], pos 4-6 -> mem2[ch]
    const bool writer = (ch < 3) && (pos < 8);
    const bool is_spk = (pos < 4);
    float* stp = out + b * OUTD + chc + (is_spk ? 0 : memoff);

    // ---- Cooperative-load offsets + padded smem slots (computed once) ----
    int offk[NLD], slotk[NLD];
#pragma unroll
    for (int k = 0; k < NLD; k++) {
        const int j   = tix + 128 * k;         // 0..767 (valid < 720)
        const int tl  = j / (BPB * IN);
        const int rem = j - tl * (BPB * IN);
        const int bll = rem / IN;
        const int ii  = rem - bll * IN;
        offk[k]  = tl * (BATCH * IN) + blockIdx.x * (BPB * IN) + rem;
        slotk[k] = (tl * BPB + bll) * ROWP + ii;
    }

    // ---- Prologue: stage chunk 0 ----
    float stage[NLD];
#pragma unroll
    for (int k = 0; k < NLD; k++)
        if (tix + 128 * k < CHF) stage[k] = __ldg(X + offk[k]);
#pragma unroll
    for (int k = 0; k < NLD; k++)
        if (tix + 128 * k < CHF) xs[0][slotk[k]] = pack2(stage[k], stage[k]);
    __syncthreads();

#pragma unroll 1
    for (int c = 0; c < NC; c++) {
        const bool more = (c + 1 < NC);
        if (more) {
            const float* xb = X + (c + 1) * cstride;
#pragma unroll
            for (int k = 0; k < NLD; k++)
                if (tix + 128 * k < CHF) stage[k] = __ldg(xb + offk[k]);
        }

        const u64* xrow = &xs[c & 1][bl * ROWP];

#pragma unroll 2
        for (int s = 0; s < CH; s++) {
            // layer 1: m = beta*m~ + b1 + x@W1slice
            u64 mp[HP];
#pragma unroll
            for (int j = 0; j < HP; j++)
                mp[j] = ffma2(BETA2, mt[j], b1p[j]);
#pragma unroll
            for (int i = 0; i < IN; i++) {
                const u64 xd = xrow[i];
#pragma unroll
                for (int j = 0; j < HP; j++)
                    mp[j] = ffma2(xd, w1p[i][j], mp[j]);
            }
            xrow += BPB * ROWP;

            // spike (integer compare, alu pipe) + reset fold + layer-2 partials
            u64 c0 = 0ull, c1 = 0ull, c2 = 0ull;
#pragma unroll
            for (int j = 0; j < HP; j++) {
                f2u m; m.u = mp[j];
                f2u sv;
                sv.f[0] = spike_i(m.f[0]);
                sv.f[1] = spike_i(m.f[1]);
                mt[j] = ffma2(sv.u, NEGINVB2, mp[j]);
                c0 = ffma2(sv.u, w2p[0][j], c0);
                c1 = ffma2(sv.u, w2p[1][j], c1);
                c2 = ffma2(sv.u, w2p[2][j], c2);
            }
            f2u a0, a1, a2;
            a0.u = c0; a1.u = c1; a2.u = c2;
            float r0 = a0.f[0] + a0.f[1];
            float r1 = a1.f[0] + a1.f[1];
            float r2 = a2.f[0] + a2.f[1];

            // levels 1,2 on all channels (quad sums)
            r0 += __shfl_xor_sync(0xffffffffu, r0, 1);
            r1 += __shfl_xor_sync(0xffffffffu, r1, 1);
            r2 += __shfl_xor_sync(0xffffffffu, r2, 1);
            r0 += __shfl_xor_sync(0xffffffffu, r0, 2);
            r1 += __shfl_xor_sync(0xffffffffu, r1, 2);
            r2 += __shfl_xor_sync(0xffffffffu, r2, 2);

            // select own channel (pos&3 invariant under xor 4/8), finish
            float v = r0;
            v = (ch == 1) ? r1 : v;
            v = (ch == 2) ? r2 : v;
            v += __shfl_xor_sync(0xffffffffu, v, 4);
            v += __shfl_xor_sync(0xffffffffu, v, 8);

            // per-lane mem2 for this lane's channel
            mloc = fmaf(0.92f, mloc, v + bk) - sloc;
            sloc = spike_i(mloc);

            if (writer) *stp = is_spk ? sloc : mloc;
            stp += orow;
        }

        if (more) {
#pragma unroll
            for (int k = 0; k < NLD; k++)
                if (tix + 128 * k < CHF)
                    xs[(c + 1) & 1][slotk[k]] = pack2(stage[k], stage[k]);
            __syncthreads();
        }
    }
}

extern "C" void kernel_launch(void* const* d_in, const int* in_sizes, int n_in,
                              void* d_out, int out_size)
{
    const float* X  = (const float*)d_in[0];
    const float* W1 = (const float*)d_in[1];
    const float* B1 = (const float*)d_in[2];
    const float* W2 = (const float*)d_in[3];
    const float* B2 = (const float*)d_in[4];
    float* out = (float*)d_out;

    snn_kernel<<<BATCH / BPB, 128>>>(X, W1, B1, W2, B2, out);  // 1024 blocks
}

// round 16
// speedup vs baseline: 1.6969x; 1.0664x over previous
#include <cuda_runtime.h>
#include <cstdint>

#define T_STEPS 1000
#define BATCH   8192
#define IN      9
#define HID     96
#define OUTD    3
#define GRP     16
#define HS      6
#define HP      3
#define CH      10                   // timesteps per staged chunk
#define NC      (T_STEPS / CH)       // 100 chunks
#define BPB     8                    // batches per block
#define BPW     2                    // batches per warp
#define ROWP    10                   // padded u64 slots per (t, batch) row
#define WCHF    (CH * BPW * IN)      // valid elements per chunk per warp = 180
#define NLDW    6                    // ceil(180/32)

typedef unsigned long long u64;

union f2u {
    u64 u;
    float f[2];
};

__device__ __forceinline__ u64 pack2(float lo, float hi) {
    f2u v; v.f[0] = lo; v.f[1] = hi; return v.u;
}
__device__ __forceinline__ u64 ffma2(u64 a, u64 b, u64 c) {
    u64 d;
    asm("fma.rn.f32x2 %0, %1, %2, %3;" : "=l"(d) : "l"(a), "l"(b), "l"(c));
    return d;
}

__global__ __launch_bounds__(128, 4)
void snn_kernel(const float* __restrict__ X,
                const float* __restrict__ W1,
                const float* __restrict__ B1,
                const float* __restrict__ W2,
                const float* __restrict__ B2,
                float* __restrict__ out)
{
    // per-warp staging regions: no block-wide barrier anywhere
    __shared__ alignas(16) u64 xs[2][4][CH * BPW * ROWP];

    const int tix  = threadIdx.x;
    const int lane = tix & 31;
    const int wid  = tix >> 5;                 // warp 0..3
    const int pos  = lane & 15;                // lane within 16-thread group
    const int gsel = lane >> 4;                // which of the warp's 2 batches
    const int bl   = wid * BPW + gsel;         // local batch 0..7
    const int b    = blockIdx.x * BPB + bl;    // global batch element
    const int hbase = pos * HS;
    const int ch   = pos & 3;                  // this lane's channel (3 = idle)
    const int chc  = (ch < 3) ? ch : 2;

    // ---- Weight slices to registers ----
    u64 w1p[IN][HP];
#pragma unroll
    for (int j = 0; j < HP; j++) {
        const int h0 = hbase + 2 * j;
#pragma unroll
        for (int i = 0; i < IN; i++)
            w1p[i][j] = pack2(W1[h0 * IN + i], W1[(h0 + 1) * IN + i]);
    }
    u64 b1p[HP];
#pragma unroll
    for (int j = 0; j < HP; j++)
        b1p[j] = pack2(B1[hbase + 2 * j], B1[hbase + 2 * j + 1]);

    u64 w2p[OUTD][HP];
#pragma unroll
    for (int o = 0; o < OUTD; o++)
#pragma unroll
        for (int j = 0; j < HP; j++)
            w2p[o][j] = pack2(W2[o * HID + hbase + 2 * j],
                              W2[o * HID + hbase + 2 * j + 1]);

    const float bk = B2[chc];

    const u64 BETA2 = 0x3F6B851F3F6B851Full;   // {0.92, 0.92}
    u64 NEGINVB2;
    { f2u v; v.f[0] = -(1.0f / 0.92f); v.f[1] = v.f[0]; NEGINVB2 = v.u; }

    // ---- State (tilde fold: m~ = m - s/beta => m_t = beta*m~ + cur) ----
    u64 mt[HP];
#pragma unroll
    for (int j = 0; j < HP; j++) mt[j] = 0ull;
    float mloc = 0.f, sloc = 0.f;

    const int orow    = BATCH * OUTD;
    const int memoff  = T_STEPS * orow;
    const int cstride = CH * BATCH * IN;

    // writer lanes: pos 0-2 -> spk2[ch], pos 4-6 -> mem2[ch]
    const bool writer = (ch < 3) && (pos < 8);
    const bool is_spk = (pos < 4);
    float* stp = out + b * OUTD + chc + (is_spk ? 0 : memoff);

    // ---- Per-warp cooperative-load offsets + smem slots (computed once) ----
    // element e = lane + 32k covers (tl, bb, ii): tl = e/18, bb = (e%18)/9, ii = e%9
    int offk[NLDW], slotk[NLDW];
#pragma unroll
    for (int k = 0; k < NLDW; k++) {
        const int e   = lane + 32 * k;         // 0..191 (valid < 180)
        const int tl  = e / (BPW * IN);
        const int rem = e - tl * (BPW * IN);
        const int bb  = rem / IN;
        const int ii  = rem - bb * IN;
        offk[k]  = tl * (BATCH * IN) + (blockIdx.x * BPB + wid * BPW + bb) * IN + ii;
        slotk[k] = (tl * BPW + bb) * ROWP + ii;
    }

    // ---- Prologue: this warp stages its own chunk 0 ----
    float stage[NLDW];
#pragma unroll
    for (int k = 0; k < NLDW; k++)
        if (lane + 32 * k < WCHF) stage[k] = __ldg(X + offk[k]);
#pragma unroll
    for (int k = 0; k < NLDW; k++)
        if (lane + 32 * k < WCHF) xs[0][wid][slotk[k]] = pack2(stage[k], stage[k]);
    __syncwarp();

#pragma unroll 1
    for (int c = 0; c < NC; c++) {
        const bool more = (c + 1 < NC);
        if (more) {
            const float* xb = X + (c + 1) * cstride;
#pragma unroll
            for (int k = 0; k < NLDW; k++)
                if (lane + 32 * k < WCHF) stage[k] = __ldg(xb + offk[k]);
        }

        const u64* xrow = &xs[c & 1][wid][gsel * ROWP];

#pragma unroll 2
        for (int s = 0; s < CH; s++) {
            // layer 1: m = beta*m~ + b1 + x@W1slice
            u64 mp[HP];
#pragma unroll
            for (int j = 0; j < HP; j++)
                mp[j] = ffma2(BETA2, mt[j], b1p[j]);
#pragma unroll
            for (int i = 0; i < IN; i++) {
                const u64 xd = xrow[i];
#pragma unroll
                for (int j = 0; j < HP; j++)
                    mp[j] = ffma2(xd, w1p[i][j], mp[j]);
            }
            xrow += BPW * ROWP;

            // spike + reset fold + layer-2 partials
            u64 c0 = 0ull, c1 = 0ull, c2 = 0ull;
#pragma unroll
            for (int j = 0; j < HP; j++) {
                f2u m; m.u = mp[j];
                f2u sv;
                sv.f[0] = (m.f[0] > 1.0f) ? 1.0f : 0.0f;
                sv.f[1] = (m.f[1] > 1.0f) ? 1.0f : 0.0f;
                mt[j] = ffma2(sv.u, NEGINVB2, mp[j]);
                c0 = ffma2(sv.u, w2p[0][j], c0);
                c1 = ffma2(sv.u, w2p[1][j], c1);
                c2 = ffma2(sv.u, w2p[2][j], c2);
            }
            f2u a0, a1, a2;
            a0.u = c0; a1.u = c1; a2.u = c2;
            float r0 = a0.f[0] + a0.f[1];
            float r1 = a1.f[0] + a1.f[1];
            float r2 = a2.f[0] + a2.f[1];

            // levels 1,2 on all channels (quad sums)
            r0 += __shfl_xor_sync(0xffffffffu, r0, 1);
            r1 += __shfl_xor_sync(0xffffffffu, r1, 1);
            r2 += __shfl_xor_sync(0xffffffffu, r2, 1);
            r0 += __shfl_xor_sync(0xffffffffu, r0, 2);
            r1 += __shfl_xor_sync(0xffffffffu, r1, 2);
            r2 += __shfl_xor_sync(0xffffffffu, r2, 2);

            // select own channel (pos&3 invariant under xor 4/8), finish
            float v = r0;
            v = (ch == 1) ? r1 : v;
            v = (ch == 2) ? r2 : v;
            v += __shfl_xor_sync(0xffffffffu, v, 4);
            v += __shfl_xor_sync(0xffffffffu, v, 8);

            // per-lane mem2 for this lane's channel
            mloc = fmaf(0.92f, mloc, v + bk) - sloc;
            sloc = (mloc > 1.0f) ? 1.0f : 0.0f;

            if (writer) *stp = is_spk ? sloc : mloc;
            stp += orow;
        }

        if (more) {
#pragma unroll
            for (int k = 0; k < NLDW; k++)
                if (lane + 32 * k < WCHF)
                    xs[(c + 1) & 1][wid][slotk[k]] = pack2(stage[k], stage[k]);
            __syncwarp();
        }
    }
}

extern "C" void kernel_launch(void* const* d_in, const int* in_sizes, int n_in,
                              void* d_out, int out_size)
{
    const float* X  = (const float*)d_in[0];
    const float* W1 = (const float*)d_in[1];
    const float* B1 = (const float*)d_in[2];
    const float* W2 = (const float*)d_in[3];
    const float* B2 = (const float*)d_in[4];
    float* out = (float*)d_out;

    snn_kernel<<<BATCH / BPB, 128>>>(X, W1, B1, W2, B2, out);  // 1024 blocks
}